// round 14
// baseline (speedup 1.0000x reference)
#include <cuda_runtime.h>
#include <cuda_fp16.h>
#include <math.h>
#include <stdint.h>

#define BB 4
#define NN 1024
#define DIM 256
#define HH 8
#define HD 32
#define FFN_DIM 1024
#define MROWS (2 * BB * NN)          // 8192 combined rows (src+tgt)
#define STREAM_ELEMS (BB * NN * DIM) // 1048576
#define SCALE 0.17677669529663687f   // 1/sqrt(32)
#define QKV 768

// ---------------- scratch (static device memory; no allocation) ----------------
__device__ __half g_xn [MROWS * DIM];
__device__ __half g_qkv[MROWS * QKV];     // packed q|k|v rows
__device__ __half g_ao [MROWS * DIM];
__device__ __half g_hh [MROWS * FFN_DIM];
__device__ __half g_wt [1048576];         // fp16 weights, transposed [N][K]
__device__ float  g_bqkv[2 * QKV];        // fused qkv bias (sa, ca)

// ---------------- weight transpose + fp16 convert: W[K,N] -> Wt[N,K] ----------------
struct WList {
    const float* src[10];
    __half* dst[10];
    int K[10];
    int N[10];
};

__global__ __launch_bounds__(256) void wcvt_kernel(WList wl) {
    int wi = blockIdx.z;
    const float* W = wl.src[wi];
    __half* Wt = wl.dst[wi];
    int K = wl.K[wi], N = wl.N[wi];
    int n0 = blockIdx.x * 32, k0 = blockIdx.y * 32;
    if (n0 >= N || k0 >= K) return;
    __shared__ float tile[32][33];
    int tx = threadIdx.x & 31, ty = threadIdx.x >> 5; // 32 x 8
#pragma unroll
    for (int i = 0; i < 32; i += 8)
        tile[ty + i][tx] = W[(size_t)(k0 + ty + i) * N + n0 + tx];
    __syncthreads();
#pragma unroll
    for (int i = 0; i < 32; i += 8)
        Wt[(size_t)(n0 + ty + i) * K + k0 + tx] = __float2half(tile[tx][ty + i]);
}

// ---------------- fused qkv bias ----------------
__global__ void bias_fuse_kernel(const float* qb, const float* kb, const float* vb,
                                 const float* qb2, const float* kb2, const float* vb2,
                                 float* dst) {
    int i = threadIdx.x;                 // 0..767
    const float* s[6] = {qb, kb, vb, qb2, kb2, vb2};
    dst[blockIdx.x * QKV + i] = s[blockIdx.x * 3 + i / 256][i & 255];
}

// ---------------- warp-per-row LayerNorm core ----------------
__device__ __forceinline__ void ln_row_warp(float4 v0, float4 v1, int lane,
                                            const float* __restrict__ g,
                                            const float* __restrict__ bta,
                                            __half* __restrict__ outrow) {
    float s  = v0.x + v0.y + v0.z + v0.w + v1.x + v1.y + v1.z + v1.w;
    float s2 = v0.x * v0.x + v0.y * v0.y + v0.z * v0.z + v0.w * v0.w
             + v1.x * v1.x + v1.y * v1.y + v1.z * v1.z + v1.w * v1.w;
#pragma unroll
    for (int o = 16; o; o >>= 1) {
        s  += __shfl_xor_sync(0xffffffffu, s,  o);
        s2 += __shfl_xor_sync(0xffffffffu, s2, o);
    }
    float mu = s * (1.f / DIM);
    float var = s2 * (1.f / DIM) - mu * mu;
    float r = rsqrtf(var + 1e-5f);
    float4 g0 = *(const float4*)&g[4 * lane];
    float4 g1 = *(const float4*)&g[128 + 4 * lane];
    float4 b0 = *(const float4*)&bta[4 * lane];
    float4 b1 = *(const float4*)&bta[128 + 4 * lane];
    __half2 h0 = __floats2half2_rn((v0.x - mu) * r * g0.x + b0.x,
                                   (v0.y - mu) * r * g0.y + b0.y);
    __half2 h1 = __floats2half2_rn((v0.z - mu) * r * g0.z + b0.z,
                                   (v0.w - mu) * r * g0.w + b0.w);
    __half2 h2 = __floats2half2_rn((v1.x - mu) * r * g1.x + b1.x,
                                   (v1.y - mu) * r * g1.y + b1.y);
    __half2 h3 = __floats2half2_rn((v1.z - mu) * r * g1.z + b1.z,
                                   (v1.w - mu) * r * g1.w + b1.w);
    *(uint2*)&outrow[4 * lane]       = make_uint2(*(uint32_t*)&h0, *(uint32_t*)&h1);
    *(uint2*)&outrow[128 + 4 * lane] = make_uint2(*(uint32_t*)&h2, *(uint32_t*)&h3);
}

// LN from res (fp32): 8 rows per block, warp per row
__global__ __launch_bounds__(256) void ln8_kernel(const float* __restrict__ x,
                                                  const float* __restrict__ g,
                                                  const float* __restrict__ bta,
                                                  __half* __restrict__ out) {
    int lane = threadIdx.x & 31;
    int row = blockIdx.x * 8 + (threadIdx.x >> 5);
    const float* xr = x + (size_t)row * DIM;
    float4 v0 = *(const float4*)&xr[4 * lane];
    float4 v1 = *(const float4*)&xr[128 + 4 * lane];
    ln_row_warp(v0, v1, lane, g, bta, out + (size_t)row * DIM);
}

// fused: res = feats (copy) AND xn = LN(feats)
__global__ __launch_bounds__(256) void ln8_init_kernel(const float* __restrict__ srcf,
                                                       const float* __restrict__ tgtf,
                                                       const float* __restrict__ g,
                                                       const float* __restrict__ bta,
                                                       float* __restrict__ res,
                                                       __half* __restrict__ out) {
    int lane = threadIdx.x & 31;
    int row = blockIdx.x * 8 + (threadIdx.x >> 5);
    const float* xr = (row < MROWS / 2 ? srcf : tgtf - (size_t)(MROWS / 2) * DIM)
                      + (size_t)row * DIM;
    float4 v0 = *(const float4*)&xr[4 * lane];
    float4 v1 = *(const float4*)&xr[128 + 4 * lane];
    float* rr = res + (size_t)row * DIM;
    *(float4*)&rr[4 * lane] = v0;
    *(float4*)&rr[128 + 4 * lane] = v1;
    ln_row_warp(v0, v1, lane, g, bta, out + (size_t)row * DIM);
}

// ---------------- common PTX helpers ----------------
__device__ __forceinline__ float gelu_exact(float x) {
    return 0.5f * x * (1.0f + erff(x * 0.70710678118654752f));
}

__device__ __forceinline__ uint32_t half2_bits(__half2 h) {
    return *(uint32_t*)&h;
}

__device__ __forceinline__ void cp16(void* dst, const void* src) {
    uint32_t s = (uint32_t)__cvta_generic_to_shared(dst);
    asm volatile("cp.async.cg.shared.global [%0], [%1], 16;" :: "r"(s), "l"(src));
}

__device__ __forceinline__ void mma_f16(float* d, const uint32_t* a, const uint32_t* b) {
    asm volatile("mma.sync.aligned.m16n8k16.row.col.f32.f16.f16.f32 "
        "{%0,%1,%2,%3}, {%4,%5,%6,%7}, {%8,%9}, {%0,%1,%2,%3};"
        : "+f"(d[0]), "+f"(d[1]), "+f"(d[2]), "+f"(d[3])
        : "r"(a[0]), "r"(a[1]), "r"(a[2]), "r"(a[3]), "r"(b[0]), "r"(b[1]));
}

__device__ __forceinline__ void ldm4(uint32_t* r, const __half* p) {
    uint32_t a = (uint32_t)__cvta_generic_to_shared(p);
    asm volatile("ldmatrix.sync.aligned.m8n8.x4.shared.b16 {%0,%1,%2,%3}, [%4];"
        : "=r"(r[0]), "=r"(r[1]), "=r"(r[2]), "=r"(r[3]) : "r"(a));
}

__device__ __forceinline__ void ldm4t(uint32_t* r, const __half* p) {
    uint32_t a = (uint32_t)__cvta_generic_to_shared(p);
    asm volatile("ldmatrix.sync.aligned.m8n8.x4.trans.shared.b16 {%0,%1,%2,%3}, [%4];"
        : "=r"(r[0]), "=r"(r[1]), "=r"(r[2]), "=r"(r[3]) : "r"(a));
}

// ---------------- fp16 tensor-core GEMM (ldmatrix mainloop, 3-stage cp.async) ----------------
// C[M,N] = A[M,K](fp16) @ Wt[N,K](fp16)^T + bias
// EPI: 0 = bias->fp16, 1 = bias+gelu->fp16, 2 = bias+residual->fp32,
//      3 = qkv-fused: fp16 out, (acc+bias)*SCALE for global n<256
// Block 128x64, 8 warps (4M x 2N), warp 32x32, K-stage 64, 3-stage pipeline.
#define ASTR 72   // halves (144 B): ldmatrix 8-row access conflict-free
#define GEMM_SMEM (3 * (128 * ASTR + 64 * ASTR) * 2)

template<int EPI>
__global__ __launch_bounds__(256, 2) void gemm_f16(const __half* __restrict__ A,
                                                   const __half* __restrict__ Wt,
                                                   const float* __restrict__ bias,
                                                   void* __restrict__ Cv,
                                                   int M, int N, int K) {
    extern __shared__ __half smh[];
    __half (*As)[128][ASTR] = (__half (*)[128][ASTR])smh;
    __half (*Bs)[64][ASTR]  = (__half (*)[64][ASTR])(smh + 3 * 128 * ASTR);

    int tid = threadIdx.x;
    int lane = tid & 31, wid = tid >> 5;
    int wm = wid >> 1, wn = wid & 1;       // 4 (M) x 2 (N)
    int gr = lane >> 2, gc = lane & 3;
    int m0 = blockIdx.y * 128, n0 = blockIdx.x * 64;

    int a_r = tid >> 1, a_c = (tid & 1) * 32;
    int b_r = tid >> 2, b_c = (tid & 3) * 16;

    int lar = wm * 32 + (lane & 15);
    int lak = (lane >> 4) * 8;
    int lbr = wn * 32 + (lane >> 4) * 8 + (lane & 7);
    int lbk = ((lane >> 3) & 1) * 8;

    float acc[2][4][4];
#pragma unroll
    for (int mt = 0; mt < 2; mt++)
#pragma unroll
        for (int nt = 0; nt < 4; nt++)
#pragma unroll
            for (int r = 0; r < 4; r++) acc[mt][nt][r] = 0.f;

    int nc = K / 64;

    auto load_stage = [&](int st, int kb) {
#pragma unroll
        for (int j = 0; j < 4; j++)
            cp16(&As[st][a_r][a_c + j * 8], &A[(size_t)(m0 + a_r) * K + kb + a_c + j * 8]);
#pragma unroll
        for (int j = 0; j < 2; j++)
            cp16(&Bs[st][b_r][b_c + j * 8], &Wt[(size_t)(n0 + b_r) * K + kb + b_c + j * 8]);
        asm volatile("cp.async.commit_group;");
    };

    load_stage(0, 0);
    load_stage(1, 64);

    for (int c = 0; c < nc; c++) {
        if (c == nc - 1) asm volatile("cp.async.wait_group 0;");
        else             asm volatile("cp.async.wait_group 1;");
        __syncthreads();

        int st = c % 3;
#pragma unroll
        for (int kk = 0; kk < 4; kk++) {
            uint32_t aF[2][4], b01[4], b23[4];
            ldm4(aF[0], &As[st][lar][kk * 16 + lak]);
            ldm4(aF[1], &As[st][lar + 16][kk * 16 + lak]);
            ldm4(b01, &Bs[st][lbr][kk * 16 + lbk]);
            ldm4(b23, &Bs[st][lbr + 16][kk * 16 + lbk]);
#pragma unroll
            for (int mt = 0; mt < 2; mt++) {
                mma_f16(acc[mt][0], aF[mt], &b01[0]);
                mma_f16(acc[mt][1], aF[mt], &b01[2]);
                mma_f16(acc[mt][2], aF[mt], &b23[0]);
                mma_f16(acc[mt][3], aF[mt], &b23[2]);
            }
        }
        __syncthreads();
        if (c + 2 < nc) load_stage((c + 2) % 3, (c + 2) * 64);
    }

    // epilogue: acc layout c0=(gr,2gc) c1=(gr,2gc+1) c2=(gr+8,2gc) c3=(gr+8,2gc+1)
#pragma unroll
    for (int mt = 0; mt < 2; mt++) {
        int mA = m0 + wm * 32 + mt * 16 + gr;
#pragma unroll
        for (int nt = 0; nt < 4; nt++) {
            int n = n0 + wn * 32 + nt * 8 + 2 * gc;
            float bx = bias[n], by = bias[n + 1];
            float sc = (EPI == 3 && n < 256) ? SCALE : 1.0f;
#pragma unroll
            for (int h = 0; h < 2; h++) {
                int m = mA + h * 8;
                float vx = acc[mt][nt][2 * h + 0] + bx;
                float vy = acc[mt][nt][2 * h + 1] + by;
                if (EPI == 1) { vx = gelu_exact(vx); vy = gelu_exact(vy); }
                if (EPI == 3) { vx *= sc; vy *= sc; }
                if (EPI == 2) {
                    float2* cp = (float2*)&((float*)Cv)[(size_t)m * N + n];
                    float2 old = *cp;
                    *cp = make_float2(vx + old.x, vy + old.y);
                } else {
                    *(__half2*)&((__half*)Cv)[(size_t)m * N + n] = __floats2half2_rn(vx, vy);
                }
            }
        }
    }
}

// ---------------- fp16 flash attention: register-resident P (FA-2 style) ----------------
// 128-query tile, 64-key chunks, 8 warps. Warp w owns S rows [16w,16w+16).
// P stays in registers: QK accumulator layout == PV A-fragment layout after half2 packing.
// smem halves: Qs[128][40], Ks[2][64][40], Vs[2][64][40]  (no S buffer)
#define ATTN_SMEM ((128 * 40 + 2 * 64 * 40 + 2 * 64 * 40) * 2)

__global__ __launch_bounds__(256, 2) void attn_mma(const __half* __restrict__ QKVp,
                                                   const float* __restrict__ bias0,
                                                   const float* __restrict__ bias1,
                                                   __half* __restrict__ O,
                                                   int kvswap) {
    extern __shared__ __half smh[];
    __half (*Qs)[40]      = (__half (*)[40])smh;
    __half (*Ks)[64][40]  = (__half (*)[64][40])(smh + 128 * 40);
    __half (*Vs)[64][40]  = (__half (*)[64][40])(smh + 128 * 40 + 2 * 64 * 40);

    int t = threadIdx.x;
    int lane = t & 31, w = t >> 5;
    int gr = lane >> 2, gc = lane & 3;
    int qbase = blockIdx.x * 128;
    int h = blockIdx.y;
    int z = blockIdx.z;
    int s = z >> 2, b = z & 3;

    const __half* qptr = QKVp + (((size_t)(s * BB + b)) * NN + qbase) * QKV + h * HD;
    int ks = s ^ kvswap;
    const __half* kptr = QKVp + ((size_t)(ks * BB + b)) * NN * QKV + 256 + h * HD;
    const __half* vptr = QKVp + ((size_t)(ks * BB + b)) * NN * QKV + 512 + h * HD;
    const float* bias = kvswap ? nullptr : (s == 0 ? bias0 : bias1);
    const float* bptr = bias ? bias + (((size_t)(b * HH + h)) * NN + qbase) * NN : nullptr;

    {   // Q: 128x32 halves (already scaled by q-proj epilogue)
        int r = t >> 1, c = (t & 1) * 16;
        cp16(&Qs[r][c],     &qptr[(size_t)r * QKV + c]);
        cp16(&Qs[r][c + 8], &qptr[(size_t)r * QKV + c + 8]);
    }
    {   // K/V chunk 0
        int r = t >> 2, c = (t & 3) * 8;
        cp16(&Ks[0][r][c], &kptr[(size_t)r * QKV + c]);
        cp16(&Vs[0][r][c], &vptr[(size_t)r * QKV + c]);
    }
    asm volatile("cp.async.commit_group;");

    float m0 = -1e30f, m1 = -1e30f, l0 = 0.f, l1 = 0.f;
    float oa[4][4];
#pragma unroll
    for (int nt = 0; nt < 4; nt++)
#pragma unroll
        for (int r = 0; r < 4; r++) oa[nt][r] = 0.f;

    int r0 = 16 * w + gr, r1 = 16 * w + gr + 8;
    int lqr = 16 * w + (lane & 15);
    int lqk = (lane >> 4) * 8;
    int lkr = (lane >> 4) * 8 + (lane & 7);
    int lkk = ((lane >> 3) & 1) * 8;
    int lvr = lane & 15;
    int lvc = ((lane >> 4) & 1) * 8;

    int buf = 0;
    for (int kc = 0; kc < 16; kc++) {
        int kb = kc * 64;
        if (kc + 1 < 16) {
            int kb2 = (kc + 1) * 64;
            int r = t >> 2, c = (t & 3) * 8;
            cp16(&Ks[buf ^ 1][r][c], &kptr[(size_t)(kb2 + r) * QKV + c]);
            cp16(&Vs[buf ^ 1][r][c], &vptr[(size_t)(kb2 + r) * QKV + c]);
            asm volatile("cp.async.commit_group;");
            asm volatile("cp.async.wait_group 1;");
        } else {
            asm volatile("cp.async.wait_group 0;");
        }
        __syncthreads();

        // ---- S = Q @ K^T (+bias) : m16 x n64, k=32 ----
        float sacc[8][4];
#pragma unroll
        for (int nt = 0; nt < 8; nt++)
#pragma unroll
            for (int r = 0; r < 4; r++) sacc[nt][r] = 0.f;

#pragma unroll
        for (int kk = 0; kk < 2; kk++) {
            uint32_t aF[4];
            ldm4(aF, &Qs[lqr][kk * 16 + lqk]);
#pragma unroll
            for (int ntp = 0; ntp < 4; ntp++) {
                uint32_t bP[4];
                ldm4(bP, &Ks[buf][ntp * 16 + lkr][kk * 16 + lkk]);
                mma_f16(sacc[ntp * 2 + 0], aF, &bP[0]);
                mma_f16(sacc[ntp * 2 + 1], aF, &bP[2]);
            }
        }
        if (bptr) {
#pragma unroll
            for (int nt = 0; nt < 8; nt++) {
                int col = kb + nt * 8 + 2 * gc;
                float2 u0 = *(const float2*)&bptr[(size_t)r0 * NN + col];
                float2 u1 = *(const float2*)&bptr[(size_t)r1 * NN + col];
                sacc[nt][0] += u0.x; sacc[nt][1] += u0.y;
                sacc[nt][2] += u1.x; sacc[nt][3] += u1.y;
            }
        }

        // ---- online softmax (rows r0, r1; quad-local) + register P pack ----
        float cm0 = -1e30f, cm1 = -1e30f;
#pragma unroll
        for (int nt = 0; nt < 8; nt++) {
            cm0 = fmaxf(cm0, fmaxf(sacc[nt][0], sacc[nt][1]));
            cm1 = fmaxf(cm1, fmaxf(sacc[nt][2], sacc[nt][3]));
        }
        cm0 = fmaxf(cm0, __shfl_xor_sync(0xffffffffu, cm0, 1));
        cm0 = fmaxf(cm0, __shfl_xor_sync(0xffffffffu, cm0, 2));
        cm1 = fmaxf(cm1, __shfl_xor_sync(0xffffffffu, cm1, 1));
        cm1 = fmaxf(cm1, __shfl_xor_sync(0xffffffffu, cm1, 2));
        float nm0 = fmaxf(m0, cm0), nm1 = fmaxf(m1, cm1);
        float f0 = __expf(m0 - nm0), f1 = __expf(m1 - nm1);
        float sum0 = 0.f, sum1 = 0.f;
        uint32_t pA[4][4];
#pragma unroll
        for (int nt = 0; nt < 8; nt++) {
            float p0 = __expf(sacc[nt][0] - nm0);
            float p1 = __expf(sacc[nt][1] - nm0);
            float p2 = __expf(sacc[nt][2] - nm1);
            float p3 = __expf(sacc[nt][3] - nm1);
            sum0 += p0 + p1; sum1 += p2 + p3;
            pA[nt >> 1][(nt & 1) * 2 + 0] = half2_bits(__floats2half2_rn(p0, p1));
            pA[nt >> 1][(nt & 1) * 2 + 1] = half2_bits(__floats2half2_rn(p2, p3));
        }
        sum0 += __shfl_xor_sync(0xffffffffu, sum0, 1);
        sum0 += __shfl_xor_sync(0xffffffffu, sum0, 2);
        sum1 += __shfl_xor_sync(0xffffffffu, sum1, 1);
        sum1 += __shfl_xor_sync(0xffffffffu, sum1, 2);
        l0 = l0 * f0 + sum0; m0 = nm0;
        l1 = l1 * f1 + sum1; m1 = nm1;
#pragma unroll
        for (int nt = 0; nt < 4; nt++) {
            oa[nt][0] *= f0; oa[nt][1] *= f0;
            oa[nt][2] *= f1; oa[nt][3] *= f1;
        }

        // ---- O += P @ V : m16 x n32, k=64 (P from registers, V via x4.trans) ----
#pragma unroll
        for (int kk = 0; kk < 4; kk++) {
            const __half* vb = &Vs[buf][kk * 16 + lvr][lvc];
            uint32_t b03[4], b47[4];
            ldm4t(b03, vb);
            ldm4t(b47, vb + 16);
            mma_f16(oa[0], pA[kk], &b03[0]);
            mma_f16(oa[1], pA[kk], &b03[2]);
            mma_f16(oa[2], pA[kk], &b47[0]);
            mma_f16(oa[3], pA[kk], &b47[2]);
        }
        __syncthreads();
        buf ^= 1;
    }

    float inv0 = 1.f / l0, inv1 = 1.f / l1;
    __half* obase = O + (((size_t)(s * BB + b)) * NN + qbase) * DIM + h * HD;
#pragma unroll
    for (int nt = 0; nt < 4; nt++) {
        int col = nt * 8 + 2 * gc;
        *(__half2*)&obase[(size_t)r0 * DIM + col] =
            __floats2half2_rn(oa[nt][0] * inv0, oa[nt][1] * inv0);
        *(__half2*)&obase[(size_t)r1 * DIM + col] =
            __floats2half2_rn(oa[nt][2] * inv1, oa[nt][3] * inv1);
    }
}

// ---------------- host orchestration ----------------
static void launch_gemm(int epi, const __half* A, const __half* Wt, const float* bias,
                        void* C, int M, int N, int K) {
    dim3 g(N / 64, M / 128);
    if (epi == 0)      gemm_f16<0><<<g, 256, GEMM_SMEM>>>(A, Wt, bias, C, M, N, K);
    else if (epi == 1) gemm_f16<1><<<g, 256, GEMM_SMEM>>>(A, Wt, bias, C, M, N, K);
    else if (epi == 2) gemm_f16<2><<<g, 256, GEMM_SMEM>>>(A, Wt, bias, C, M, N, K);
    else               gemm_f16<3><<<g, 256, GEMM_SMEM>>>(A, Wt, bias, C, M, N, K);
}

extern "C" void kernel_launch(void* const* d_in, const int* in_sizes, int n_in,
                              void* d_out, int out_size) {
    const float* src_feats = (const float*)d_in[0];
    const float* tgt_feats = (const float*)d_in[1];
    const float* src_bias  = (const float*)d_in[2];
    const float* tgt_bias  = (const float*)d_in[3];
    const float* sa_q_w = (const float*)d_in[4];  const float* sa_q_b = (const float*)d_in[5];
    const float* sa_k_w = (const float*)d_in[6];  const float* sa_k_b = (const float*)d_in[7];
    const float* sa_v_w = (const float*)d_in[8];  const float* sa_v_b = (const float*)d_in[9];
    const float* sa_o_w = (const float*)d_in[10]; const float* sa_o_b = (const float*)d_in[11];
    const float* ca_q_w = (const float*)d_in[12]; const float* ca_q_b = (const float*)d_in[13];
    const float* ca_k_w = (const float*)d_in[14]; const float* ca_k_b = (const float*)d_in[15];
    const float* ca_v_w = (const float*)d_in[16]; const float* ca_v_b = (const float*)d_in[17];
    const float* ca_o_w = (const float*)d_in[18]; const float* ca_o_b = (const float*)d_in[19];
    const float* ln_sa_g = (const float*)d_in[20]; const float* ln_sa_b = (const float*)d_in[21];
    const float* ln_ca_g = (const float*)d_in[22]; const float* ln_ca_b = (const float*)d_in[23];
    const float* ln_ff_g = (const float*)d_in[24]; const float* ln_ff_b = (const float*)d_in[25];
    const float* ffn_w1 = (const float*)d_in[26]; const float* ffn_b1 = (const float*)d_in[27];
    const float* ffn_w2 = (const float*)d_in[28]; const float* ffn_b2 = (const float*)d_in[29];

    float* res = (float*)d_out; // [2, B, N, DIM]

    cudaFuncSetAttribute(gemm_f16<0>, cudaFuncAttributeMaxDynamicSharedMemorySize, GEMM_SMEM);
    cudaFuncSetAttribute(gemm_f16<1>, cudaFuncAttributeMaxDynamicSharedMemorySize, GEMM_SMEM);
    cudaFuncSetAttribute(gemm_f16<2>, cudaFuncAttributeMaxDynamicSharedMemorySize, GEMM_SMEM);
    cudaFuncSetAttribute(gemm_f16<3>, cudaFuncAttributeMaxDynamicSharedMemorySize, GEMM_SMEM);
    cudaFuncSetAttribute(attn_mma,    cudaFuncAttributeMaxDynamicSharedMemorySize, ATTN_SMEM);

    void *p_xn, *p_qkv, *p_ao, *p_h, *p_wt, *p_bq;
    cudaGetSymbolAddress(&p_xn,  g_xn);
    cudaGetSymbolAddress(&p_qkv, g_qkv);
    cudaGetSymbolAddress(&p_ao,  g_ao);
    cudaGetSymbolAddress(&p_h,   g_hh);
    cudaGetSymbolAddress(&p_wt,  g_wt);
    cudaGetSymbolAddress(&p_bq,  g_bqkv);
    __half* xn  = (__half*)p_xn;
    __half* qkv = (__half*)p_qkv;
    __half* ao  = (__half*)p_ao;
    __half* hb  = (__half*)p_h;
    __half* wt  = (__half*)p_wt;
    float*  bq  = (float*)p_bq;

    __half* wt_saqkv = wt;                        // [768][256]
    __half* wt_caqkv = wt + 196608;               // [768][256]
    __half* wt_sao   = wt + 393216;               // [256][256]
    __half* wt_cao   = wt + 458752;               // [256][256]
    __half* wt_w1    = wt + 524288;               // [1024][256]
    __half* wt_w2    = wt + 786432;               // [256][1024]

    WList wl;
    const float* srcs[10] = {sa_q_w, sa_k_w, sa_v_w, ca_q_w, ca_k_w, ca_v_w,
                             sa_o_w, ca_o_w, ffn_w1, ffn_w2};
    __half* dsts[10] = {wt_saqkv, wt_saqkv + 256 * 256, wt_saqkv + 512 * 256,
                        wt_caqkv, wt_caqkv + 256 * 256, wt_caqkv + 512 * 256,
                        wt_sao, wt_cao, wt_w1, wt_w2};
    int Ksz[10] = {256, 256, 256, 256, 256, 256, 256, 256, 256, 1024};
    int Nsz[10] = {256, 256, 256, 256, 256, 256, 256, 256, 1024, 256};
    for (int i = 0; i < 10; i++) { wl.src[i] = srcs[i]; wl.dst[i] = dsts[i]; wl.K[i] = Ksz[i]; wl.N[i] = Nsz[i]; }
    wcvt_kernel<<<dim3(32, 32, 10), 256>>>(wl);
    bias_fuse_kernel<<<2, QKV>>>(sa_q_b, sa_k_b, sa_v_b, ca_q_b, ca_k_b, ca_v_b, bq);

    dim3 agrid(NN / 128, HH, 2 * BB);

    // ---- 1. geometric self-attention ----
    ln8_init_kernel<<<MROWS / 8, 256>>>(src_feats, tgt_feats, ln_sa_g, ln_sa_b, res, xn);
    launch_gemm(3, xn, wt_saqkv, bq, qkv, MROWS, QKV, DIM);
    attn_mma<<<agrid, 256, ATTN_SMEM>>>(qkv, src_bias, tgt_bias, ao, 0);
    launch_gemm(2, ao, wt_sao, sa_o_b, res, MROWS, DIM, DIM);

    // ---- 2. cross-attention ----
    ln8_kernel<<<MROWS / 8, 256>>>(res, ln_ca_g, ln_ca_b, xn);
    launch_gemm(3, xn, wt_caqkv, bq + QKV, qkv, MROWS, QKV, DIM);
    attn_mma<<<agrid, 256, ATTN_SMEM>>>(qkv, nullptr, nullptr, ao, 1);
    launch_gemm(2, ao, wt_cao, ca_o_b, res, MROWS, DIM, DIM);

    // ---- 3. FFN ----
    ln8_kernel<<<MROWS / 8, 256>>>(res, ln_ff_g, ln_ff_b, xn);
    launch_gemm(1, xn, wt_w1, ffn_b1, hb, MROWS, FFN_DIM, DIM);
    launch_gemm(2, hb, wt_w2, ffn_b2, res, MROWS, DIM, FFN_DIM);
}

// round 15
// speedup vs baseline: 1.4855x; 1.4855x over previous
#include <cuda_runtime.h>
#include <cuda_fp16.h>
#include <math.h>
#include <stdint.h>

#define BB 4
#define NN 1024
#define DIM 256
#define HH 8
#define HD 32
#define FFN_DIM 1024
#define MROWS (2 * BB * NN)          // 8192 combined rows (src+tgt)
#define STREAM_ELEMS (BB * NN * DIM) // 1048576
#define SCALE 0.17677669529663687f   // 1/sqrt(32)
#define QKV 768

// ---------------- scratch (static device memory; no allocation) ----------------
__device__ __half g_xn [MROWS * DIM];
__device__ __half g_qkv[MROWS * QKV];     // packed q|k|v rows
__device__ __half g_ao [MROWS * DIM];
__device__ __half g_hh [MROWS * FFN_DIM];
__device__ __half g_wt [1048576];         // fp16 weights, transposed [N][K]
__device__ float  g_bqkv[2 * QKV];        // fused qkv bias (sa, ca)

// ---------------- residual init: res = feats ----------------
__global__ void copy_feats_kernel(const float4* __restrict__ a,
                                  const float4* __restrict__ b,
                                  float4* __restrict__ out) {
    int i = blockIdx.x * blockDim.x + threadIdx.x;
    out[i] = a[i];
    out[i + STREAM_ELEMS / 4] = b[i];
}

// ---------------- weight transpose + fp16 convert: W[K,N] -> Wt[N,K] ----------------
struct WList {
    const float* src[10];
    __half* dst[10];
    int K[10];
    int N[10];
};

__global__ __launch_bounds__(256) void wcvt_kernel(WList wl) {
    int wi = blockIdx.z;
    const float* W = wl.src[wi];
    __half* Wt = wl.dst[wi];
    int K = wl.K[wi], N = wl.N[wi];
    int n0 = blockIdx.x * 32, k0 = blockIdx.y * 32;
    if (n0 >= N || k0 >= K) return;
    __shared__ float tile[32][33];
    int tx = threadIdx.x & 31, ty = threadIdx.x >> 5; // 32 x 8
#pragma unroll
    for (int i = 0; i < 32; i += 8)
        tile[ty + i][tx] = W[(size_t)(k0 + ty + i) * N + n0 + tx];
    __syncthreads();
#pragma unroll
    for (int i = 0; i < 32; i += 8)
        Wt[(size_t)(n0 + ty + i) * K + k0 + tx] = __float2half(tile[tx][ty + i]);
}

// ---------------- fused qkv bias ----------------
__global__ void bias_fuse_kernel(const float* qb, const float* kb, const float* vb,
                                 const float* qb2, const float* kb2, const float* vb2,
                                 float* dst) {
    int i = threadIdx.x;                 // 0..767
    const float* s[6] = {qb, kb, vb, qb2, kb2, vb2};
    dst[blockIdx.x * QKV + i] = s[blockIdx.x * 3 + i / 256][i & 255];
}

// ---------------- warp-per-row LayerNorm: 8 rows per 256-thr block ----------------
__global__ __launch_bounds__(256) void ln8_kernel(const float* __restrict__ x,
                                                  const float* __restrict__ g,
                                                  const float* __restrict__ bta,
                                                  __half* __restrict__ out) {
    int lane = threadIdx.x & 31;
    int row = blockIdx.x * 8 + (threadIdx.x >> 5);
    const float* xr = x + (size_t)row * DIM;
    float4 v0 = *(const float4*)&xr[4 * lane];
    float4 v1 = *(const float4*)&xr[128 + 4 * lane];

    float s  = v0.x + v0.y + v0.z + v0.w + v1.x + v1.y + v1.z + v1.w;
    float s2 = v0.x * v0.x + v0.y * v0.y + v0.z * v0.z + v0.w * v0.w
             + v1.x * v1.x + v1.y * v1.y + v1.z * v1.z + v1.w * v1.w;
#pragma unroll
    for (int o = 16; o; o >>= 1) {
        s  += __shfl_xor_sync(0xffffffffu, s,  o);
        s2 += __shfl_xor_sync(0xffffffffu, s2, o);
    }
    float mu = s * (1.f / DIM);
    float var = s2 * (1.f / DIM) - mu * mu;
    float r = rsqrtf(var + 1e-5f);

    float4 g0 = *(const float4*)&g[4 * lane];
    float4 g1 = *(const float4*)&g[128 + 4 * lane];
    float4 b0 = *(const float4*)&bta[4 * lane];
    float4 b1 = *(const float4*)&bta[128 + 4 * lane];
    __half* outrow = out + (size_t)row * DIM;
    __half2 h0 = __floats2half2_rn((v0.x - mu) * r * g0.x + b0.x,
                                   (v0.y - mu) * r * g0.y + b0.y);
    __half2 h1 = __floats2half2_rn((v0.z - mu) * r * g0.z + b0.z,
                                   (v0.w - mu) * r * g0.w + b0.w);
    __half2 h2 = __floats2half2_rn((v1.x - mu) * r * g1.x + b1.x,
                                   (v1.y - mu) * r * g1.y + b1.y);
    __half2 h3 = __floats2half2_rn((v1.z - mu) * r * g1.z + b1.z,
                                   (v1.w - mu) * r * g1.w + b1.w);
    *(uint2*)&outrow[4 * lane]       = make_uint2(*(uint32_t*)&h0, *(uint32_t*)&h1);
    *(uint2*)&outrow[128 + 4 * lane] = make_uint2(*(uint32_t*)&h2, *(uint32_t*)&h3);
}

// ---------------- common PTX helpers ----------------
__device__ __forceinline__ float gelu_exact(float x) {
    return 0.5f * x * (1.0f + erff(x * 0.70710678118654752f));
}

__device__ __forceinline__ uint32_t half2_bits(__half2 h) {
    return *(uint32_t*)&h;
}

__device__ __forceinline__ void cp16(void* dst, const void* src) {
    uint32_t s = (uint32_t)__cvta_generic_to_shared(dst);
    asm volatile("cp.async.cg.shared.global [%0], [%1], 16;" :: "r"(s), "l"(src));
}

__device__ __forceinline__ void mma_f16(float* d, const uint32_t* a, const uint32_t* b) {
    asm volatile("mma.sync.aligned.m16n8k16.row.col.f32.f16.f16.f32 "
        "{%0,%1,%2,%3}, {%4,%5,%6,%7}, {%8,%9}, {%0,%1,%2,%3};"
        : "+f"(d[0]), "+f"(d[1]), "+f"(d[2]), "+f"(d[3])
        : "r"(a[0]), "r"(a[1]), "r"(a[2]), "r"(a[3]), "r"(b[0]), "r"(b[1]));
}

__device__ __forceinline__ void ldm4(uint32_t* r, const __half* p) {
    uint32_t a = (uint32_t)__cvta_generic_to_shared(p);
    asm volatile("ldmatrix.sync.aligned.m8n8.x4.shared.b16 {%0,%1,%2,%3}, [%4];"
        : "=r"(r[0]), "=r"(r[1]), "=r"(r[2]), "=r"(r[3]) : "r"(a));
}

__device__ __forceinline__ void ldm4t(uint32_t* r, const __half* p) {
    uint32_t a = (uint32_t)__cvta_generic_to_shared(p);
    asm volatile("ldmatrix.sync.aligned.m8n8.x4.trans.shared.b16 {%0,%1,%2,%3}, [%4];"
        : "=r"(r[0]), "=r"(r[1]), "=r"(r[2]), "=r"(r[3]) : "r"(a));
}

// ---------------- fp16 tensor-core GEMM (ldmatrix mainloop, 3-stage cp.async) ----------------
// C[M,N] = A[M,K](fp16) @ Wt[N,K](fp16)^T + bias
// EPI: 0 = bias->fp16, 1 = bias+gelu->fp16, 2 = bias+residual->fp32,
//      3 = qkv-fused: fp16 out, (acc+bias)*SCALE for global n<256
// Block 128x64, 8 warps (4M x 2N), warp 32x32, K-stage 64, 3-stage pipeline.
#define ASTR 72   // halves (144 B): ldmatrix 8-row access conflict-free
#define GEMM_SMEM (3 * (128 * ASTR + 64 * ASTR) * 2)

template<int EPI>
__global__ __launch_bounds__(256, 2) void gemm_f16(const __half* __restrict__ A,
                                                   const __half* __restrict__ Wt,
                                                   const float* __restrict__ bias,
                                                   void* __restrict__ Cv,
                                                   int M, int N, int K) {
    extern __shared__ __half smh[];
    __half (*As)[128][ASTR] = (__half (*)[128][ASTR])smh;
    __half (*Bs)[64][ASTR]  = (__half (*)[64][ASTR])(smh + 3 * 128 * ASTR);

    int tid = threadIdx.x;
    int lane = tid & 31, wid = tid >> 5;
    int wm = wid >> 1, wn = wid & 1;       // 4 (M) x 2 (N)
    int gr = lane >> 2, gc = lane & 3;
    int m0 = blockIdx.y * 128, n0 = blockIdx.x * 64;

    int a_r = tid >> 1, a_c = (tid & 1) * 32;
    int b_r = tid >> 2, b_c = (tid & 3) * 16;

    int lar = wm * 32 + (lane & 15);
    int lak = (lane >> 4) * 8;
    int lbr = wn * 32 + (lane >> 4) * 8 + (lane & 7);
    int lbk = ((lane >> 3) & 1) * 8;

    float acc[2][4][4];
#pragma unroll
    for (int mt = 0; mt < 2; mt++)
#pragma unroll
        for (int nt = 0; nt < 4; nt++)
#pragma unroll
            for (int r = 0; r < 4; r++) acc[mt][nt][r] = 0.f;

    int nc = K / 64;

    auto load_stage = [&](int st, int kb) {
#pragma unroll
        for (int j = 0; j < 4; j++)
            cp16(&As[st][a_r][a_c + j * 8], &A[(size_t)(m0 + a_r) * K + kb + a_c + j * 8]);
#pragma unroll
        for (int j = 0; j < 2; j++)
            cp16(&Bs[st][b_r][b_c + j * 8], &Wt[(size_t)(n0 + b_r) * K + kb + b_c + j * 8]);
        asm volatile("cp.async.commit_group;");
    };

    load_stage(0, 0);
    load_stage(1, 64);

    for (int c = 0; c < nc; c++) {
        if (c == nc - 1) asm volatile("cp.async.wait_group 0;");
        else             asm volatile("cp.async.wait_group 1;");
        __syncthreads();

        int st = c % 3;
#pragma unroll
        for (int kk = 0; kk < 4; kk++) {
            uint32_t aF[2][4], b01[4], b23[4];
            ldm4(aF[0], &As[st][lar][kk * 16 + lak]);
            ldm4(aF[1], &As[st][lar + 16][kk * 16 + lak]);
            ldm4(b01, &Bs[st][lbr][kk * 16 + lbk]);
            ldm4(b23, &Bs[st][lbr + 16][kk * 16 + lbk]);
#pragma unroll
            for (int mt = 0; mt < 2; mt++) {
                mma_f16(acc[mt][0], aF[mt], &b01[0]);
                mma_f16(acc[mt][1], aF[mt], &b01[2]);
                mma_f16(acc[mt][2], aF[mt], &b23[0]);
                mma_f16(acc[mt][3], aF[mt], &b23[2]);
            }
        }
        __syncthreads();
        if (c + 2 < nc) load_stage((c + 2) % 3, (c + 2) * 64);
    }

    // epilogue: acc layout c0=(gr,2gc) c1=(gr,2gc+1) c2=(gr+8,2gc) c3=(gr+8,2gc+1)
#pragma unroll
    for (int mt = 0; mt < 2; mt++) {
        int mA = m0 + wm * 32 + mt * 16 + gr;
#pragma unroll
        for (int nt = 0; nt < 4; nt++) {
            int n = n0 + wn * 32 + nt * 8 + 2 * gc;
            float bx = bias[n], by = bias[n + 1];
            float sc = (EPI == 3 && n < 256) ? SCALE : 1.0f;
#pragma unroll
            for (int h = 0; h < 2; h++) {
                int m = mA + h * 8;
                float vx = acc[mt][nt][2 * h + 0] + bx;
                float vy = acc[mt][nt][2 * h + 1] + by;
                if (EPI == 1) { vx = gelu_exact(vx); vy = gelu_exact(vy); }
                if (EPI == 3) { vx *= sc; vy *= sc; }
                if (EPI == 2) {
                    float2* cp = (float2*)&((float*)Cv)[(size_t)m * N + n];
                    float2 old = *cp;
                    *cp = make_float2(vx + old.x, vy + old.y);
                } else {
                    *(__half2*)&((__half*)Cv)[(size_t)m * N + n] = __floats2half2_rn(vx, vy);
                }
            }
        }
    }
}

// ---------------- fp16 flash attention: register-resident P (FA-2 style) ----------------
// 128-query tile, 64-key chunks, 8 warps. Warp w owns S rows [16w,16w+16).
// P stays in registers: QK accumulator layout == PV A-fragment layout after half2 packing.
// smem halves: Qs[128][40], Ks[2][64][40], Vs[2][64][40]  (no S buffer)
#define ATTN_SMEM ((128 * 40 + 2 * 64 * 40 + 2 * 64 * 40) * 2)

__global__ __launch_bounds__(256, 2) void attn_mma(const __half* __restrict__ QKVp,
                                                   const float* __restrict__ bias0,
                                                   const float* __restrict__ bias1,
                                                   __half* __restrict__ O,
                                                   int kvswap) {
    extern __shared__ __half smh[];
    __half (*Qs)[40]      = (__half (*)[40])smh;
    __half (*Ks)[64][40]  = (__half (*)[64][40])(smh + 128 * 40);
    __half (*Vs)[64][40]  = (__half (*)[64][40])(smh + 128 * 40 + 2 * 64 * 40);

    int t = threadIdx.x;
    int lane = t & 31, w = t >> 5;
    int gr = lane >> 2, gc = lane & 3;
    int qbase = blockIdx.x * 128;
    int h = blockIdx.y;
    int z = blockIdx.z;
    int s = z >> 2, b = z & 3;

    const __half* qptr = QKVp + (((size_t)(s * BB + b)) * NN + qbase) * QKV + h * HD;
    int ks = s ^ kvswap;
    const __half* kptr = QKVp + ((size_t)(ks * BB + b)) * NN * QKV + 256 + h * HD;
    const __half* vptr = QKVp + ((size_t)(ks * BB + b)) * NN * QKV + 512 + h * HD;
    const float* bias = kvswap ? nullptr : (s == 0 ? bias0 : bias1);
    const float* bptr = bias ? bias + (((size_t)(b * HH + h)) * NN + qbase) * NN : nullptr;

    {   // Q: 128x32 halves (already scaled by q-proj epilogue)
        int r = t >> 1, c = (t & 1) * 16;
        cp16(&Qs[r][c],     &qptr[(size_t)r * QKV + c]);
        cp16(&Qs[r][c + 8], &qptr[(size_t)r * QKV + c + 8]);
    }
    {   // K/V chunk 0
        int r = t >> 2, c = (t & 3) * 8;
        cp16(&Ks[0][r][c], &kptr[(size_t)r * QKV + c]);
        cp16(&Vs[0][r][c], &vptr[(size_t)r * QKV + c]);
    }
    asm volatile("cp.async.commit_group;");

    float m0 = -1e30f, m1 = -1e30f, l0 = 0.f, l1 = 0.f;
    float oa[4][4];
#pragma unroll
    for (int nt = 0; nt < 4; nt++)
#pragma unroll
        for (int r = 0; r < 4; r++) oa[nt][r] = 0.f;

    int r0 = 16 * w + gr, r1 = 16 * w + gr + 8;
    int lqr = 16 * w + (lane & 15);
    int lqk = (lane >> 4) * 8;
    int lkr = (lane >> 4) * 8 + (lane & 7);
    int lkk = ((lane >> 3) & 1) * 8;
    int lvr = lane & 15;
    int lvc = ((lane >> 4) & 1) * 8;

    int buf = 0;
    for (int kc = 0; kc < 16; kc++) {
        int kb = kc * 64;
        if (kc + 1 < 16) {
            int kb2 = (kc + 1) * 64;
            int r = t >> 2, c = (t & 3) * 8;
            cp16(&Ks[buf ^ 1][r][c], &kptr[(size_t)(kb2 + r) * QKV + c]);
            cp16(&Vs[buf ^ 1][r][c], &vptr[(size_t)(kb2 + r) * QKV + c]);
            asm volatile("cp.async.commit_group;");
            asm volatile("cp.async.wait_group 1;");
        } else {
            asm volatile("cp.async.wait_group 0;");
        }
        __syncthreads();

        // ---- S = Q @ K^T (+bias) : m16 x n64, k=32 ----
        float sacc[8][4];
#pragma unroll
        for (int nt = 0; nt < 8; nt++)
#pragma unroll
            for (int r = 0; r < 4; r++) sacc[nt][r] = 0.f;

#pragma unroll
        for (int kk = 0; kk < 2; kk++) {
            uint32_t aF[4];
            ldm4(aF, &Qs[lqr][kk * 16 + lqk]);
#pragma unroll
            for (int ntp = 0; ntp < 4; ntp++) {
                uint32_t bP[4];
                ldm4(bP, &Ks[buf][ntp * 16 + lkr][kk * 16 + lkk]);
                mma_f16(sacc[ntp * 2 + 0], aF, &bP[0]);
                mma_f16(sacc[ntp * 2 + 1], aF, &bP[2]);
            }
        }
        if (bptr) {
#pragma unroll
            for (int nt = 0; nt < 8; nt++) {
                int col = kb + nt * 8 + 2 * gc;
                float2 u0 = *(const float2*)&bptr[(size_t)r0 * NN + col];
                float2 u1 = *(const float2*)&bptr[(size_t)r1 * NN + col];
                sacc[nt][0] += u0.x; sacc[nt][1] += u0.y;
                sacc[nt][2] += u1.x; sacc[nt][3] += u1.y;
            }
        }

        // ---- online softmax (rows r0, r1; quad-local) + register P pack ----
        float cm0 = -1e30f, cm1 = -1e30f;
#pragma unroll
        for (int nt = 0; nt < 8; nt++) {
            cm0 = fmaxf(cm0, fmaxf(sacc[nt][0], sacc[nt][1]));
            cm1 = fmaxf(cm1, fmaxf(sacc[nt][2], sacc[nt][3]));
        }
        cm0 = fmaxf(cm0, __shfl_xor_sync(0xffffffffu, cm0, 1));
        cm0 = fmaxf(cm0, __shfl_xor_sync(0xffffffffu, cm0, 2));
        cm1 = fmaxf(cm1, __shfl_xor_sync(0xffffffffu, cm1, 1));
        cm1 = fmaxf(cm1, __shfl_xor_sync(0xffffffffu, cm1, 2));
        float nm0 = fmaxf(m0, cm0), nm1 = fmaxf(m1, cm1);
        float f0 = __expf(m0 - nm0), f1 = __expf(m1 - nm1);
        float sum0 = 0.f, sum1 = 0.f;
        uint32_t pA[4][4];
#pragma unroll
        for (int nt = 0; nt < 8; nt++) {
            float p0 = __expf(sacc[nt][0] - nm0);
            float p1 = __expf(sacc[nt][1] - nm0);
            float p2 = __expf(sacc[nt][2] - nm1);
            float p3 = __expf(sacc[nt][3] - nm1);
            sum0 += p0 + p1; sum1 += p2 + p3;
            pA[nt >> 1][(nt & 1) * 2 + 0] = half2_bits(__floats2half2_rn(p0, p1));
            pA[nt >> 1][(nt & 1) * 2 + 1] = half2_bits(__floats2half2_rn(p2, p3));
        }
        sum0 += __shfl_xor_sync(0xffffffffu, sum0, 1);
        sum0 += __shfl_xor_sync(0xffffffffu, sum0, 2);
        sum1 += __shfl_xor_sync(0xffffffffu, sum1, 1);
        sum1 += __shfl_xor_sync(0xffffffffu, sum1, 2);
        l0 = l0 * f0 + sum0; m0 = nm0;
        l1 = l1 * f1 + sum1; m1 = nm1;
#pragma unroll
        for (int nt = 0; nt < 4; nt++) {
            oa[nt][0] *= f0; oa[nt][1] *= f0;
            oa[nt][2] *= f1; oa[nt][3] *= f1;
        }

        // ---- O += P @ V : m16 x n32, k=64 (P from registers, V via x4.trans) ----
#pragma unroll
        for (int kk = 0; kk < 4; kk++) {
            const __half* vb = &Vs[buf][kk * 16 + lvr][lvc];
            uint32_t b03[4], b47[4];
            ldm4t(b03, vb);
            ldm4t(b47, vb + 16);
            mma_f16(oa[0], pA[kk], &b03[0]);
            mma_f16(oa[1], pA[kk], &b03[2]);
            mma_f16(oa[2], pA[kk], &b47[0]);
            mma_f16(oa[3], pA[kk], &b47[2]);
        }
        __syncthreads();
        buf ^= 1;
    }

    float inv0 = 1.f / l0, inv1 = 1.f / l1;
    __half* obase = O + (((size_t)(s * BB + b)) * NN + qbase) * DIM + h * HD;
#pragma unroll
    for (int nt = 0; nt < 4; nt++) {
        int col = nt * 8 + 2 * gc;
        *(__half2*)&obase[(size_t)r0 * DIM + col] =
            __floats2half2_rn(oa[nt][0] * inv0, oa[nt][1] * inv0);
        *(__half2*)&obase[(size_t)r1 * DIM + col] =
            __floats2half2_rn(oa[nt][2] * inv1, oa[nt][3] * inv1);
    }
}

// ---------------- host orchestration ----------------
static void launch_gemm(int epi, const __half* A, const __half* Wt, const float* bias,
                        void* C, int M, int N, int K) {
    dim3 g(N / 64, M / 128);
    if (epi == 0)      gemm_f16<0><<<g, 256, GEMM_SMEM>>>(A, Wt, bias, C, M, N, K);
    else if (epi == 1) gemm_f16<1><<<g, 256, GEMM_SMEM>>>(A, Wt, bias, C, M, N, K);
    else if (epi == 2) gemm_f16<2><<<g, 256, GEMM_SMEM>>>(A, Wt, bias, C, M, N, K);
    else               gemm_f16<3><<<g, 256, GEMM_SMEM>>>(A, Wt, bias, C, M, N, K);
}

extern "C" void kernel_launch(void* const* d_in, const int* in_sizes, int n_in,
                              void* d_out, int out_size) {
    const float* src_feats = (const float*)d_in[0];
    const float* tgt_feats = (const float*)d_in[1];
    const float* src_bias  = (const float*)d_in[2];
    const float* tgt_bias  = (const float*)d_in[3];
    const float* sa_q_w = (const float*)d_in[4];  const float* sa_q_b = (const float*)d_in[5];
    const float* sa_k_w = (const float*)d_in[6];  const float* sa_k_b = (const float*)d_in[7];
    const float* sa_v_w = (const float*)d_in[8];  const float* sa_v_b = (const float*)d_in[9];
    const float* sa_o_w = (const float*)d_in[10]; const float* sa_o_b = (const float*)d_in[11];
    const float* ca_q_w = (const float*)d_in[12]; const float* ca_q_b = (const float*)d_in[13];
    const float* ca_k_w = (const float*)d_in[14]; const float* ca_k_b = (const float*)d_in[15];
    const float* ca_v_w = (const float*)d_in[16]; const float* ca_v_b = (const float*)d_in[17];
    const float* ca_o_w = (const float*)d_in[18]; const float* ca_o_b = (const float*)d_in[19];
    const float* ln_sa_g = (const float*)d_in[20]; const float* ln_sa_b = (const float*)d_in[21];
    const float* ln_ca_g = (const float*)d_in[22]; const float* ln_ca_b = (const float*)d_in[23];
    const float* ln_ff_g = (const float*)d_in[24]; const float* ln_ff_b = (const float*)d_in[25];
    const float* ffn_w1 = (const float*)d_in[26]; const float* ffn_b1 = (const float*)d_in[27];
    const float* ffn_w2 = (const float*)d_in[28]; const float* ffn_b2 = (const float*)d_in[29];

    float* res = (float*)d_out; // [2, B, N, DIM]

    cudaFuncSetAttribute(gemm_f16<0>, cudaFuncAttributeMaxDynamicSharedMemorySize, GEMM_SMEM);
    cudaFuncSetAttribute(gemm_f16<1>, cudaFuncAttributeMaxDynamicSharedMemorySize, GEMM_SMEM);
    cudaFuncSetAttribute(gemm_f16<2>, cudaFuncAttributeMaxDynamicSharedMemorySize, GEMM_SMEM);
    cudaFuncSetAttribute(gemm_f16<3>, cudaFuncAttributeMaxDynamicSharedMemorySize, GEMM_SMEM);
    cudaFuncSetAttribute(attn_mma,    cudaFuncAttributeMaxDynamicSharedMemorySize, ATTN_SMEM);

    void *p_xn, *p_qkv, *p_ao, *p_h, *p_wt, *p_bq;
    cudaGetSymbolAddress(&p_xn,  g_xn);
    cudaGetSymbolAddress(&p_qkv, g_qkv);
    cudaGetSymbolAddress(&p_ao,  g_ao);
    cudaGetSymbolAddress(&p_h,   g_hh);
    cudaGetSymbolAddress(&p_wt,  g_wt);
    cudaGetSymbolAddress(&p_bq,  g_bqkv);
    __half* xn  = (__half*)p_xn;
    __half* qkv = (__half*)p_qkv;
    __half* ao  = (__half*)p_ao;
    __half* hb  = (__half*)p_h;
    __half* wt  = (__half*)p_wt;
    float*  bq  = (float*)p_bq;

    __half* wt_saqkv = wt;                        // [768][256]
    __half* wt_caqkv = wt + 196608;               // [768][256]
    __half* wt_sao   = wt + 393216;               // [256][256]
    __half* wt_cao   = wt + 458752;               // [256][256]
    __half* wt_w1    = wt + 524288;               // [1024][256]
    __half* wt_w2    = wt + 786432;               // [256][1024]

    WList wl;
    const float* srcs[10] = {sa_q_w, sa_k_w, sa_v_w, ca_q_w, ca_k_w, ca_v_w,
                             sa_o_w, ca_o_w, ffn_w1, ffn_w2};
    __half* dsts[10] = {wt_saqkv, wt_saqkv + 256 * 256, wt_saqkv + 512 * 256,
                        wt_caqkv, wt_caqkv + 256 * 256, wt_caqkv + 512 * 256,
                        wt_sao, wt_cao, wt_w1, wt_w2};
    int Ksz[10] = {256, 256, 256, 256, 256, 256, 256, 256, 256, 1024};
    int Nsz[10] = {256, 256, 256, 256, 256, 256, 256, 256, 1024, 256};
    for (int i = 0; i < 10; i++) { wl.src[i] = srcs[i]; wl.dst[i] = dsts[i]; wl.K[i] = Ksz[i]; wl.N[i] = Nsz[i]; }
    wcvt_kernel<<<dim3(32, 32, 10), 256>>>(wl);
    bias_fuse_kernel<<<2, QKV>>>(sa_q_b, sa_k_b, sa_v_b, ca_q_b, ca_k_b, ca_v_b, bq);

    copy_feats_kernel<<<STREAM_ELEMS / 4 / 256, 256>>>(
        (const float4*)src_feats, (const float4*)tgt_feats, (float4*)res);

    dim3 agrid(NN / 128, HH, 2 * BB);

    // ---- 1. geometric self-attention ----
    ln8_kernel<<<MROWS / 8, 256>>>(res, ln_sa_g, ln_sa_b, xn);
    launch_gemm(3, xn, wt_saqkv, bq, qkv, MROWS, QKV, DIM);
    attn_mma<<<agrid, 256, ATTN_SMEM>>>(qkv, src_bias, tgt_bias, ao, 0);
    launch_gemm(2, ao, wt_sao, sa_o_b, res, MROWS, DIM, DIM);

    // ---- 2. cross-attention ----
    ln8_kernel<<<MROWS / 8, 256>>>(res, ln_ca_g, ln_ca_b, xn);
    launch_gemm(3, xn, wt_caqkv, bq + QKV, qkv, MROWS, QKV, DIM);
    attn_mma<<<agrid, 256, ATTN_SMEM>>>(qkv, nullptr, nullptr, ao, 1);
    launch_gemm(2, ao, wt_cao, ca_o_b, res, MROWS, DIM, DIM);

    // ---- 3. FFN ----
    ln8_kernel<<<MROWS / 8, 256>>>(res, ln_ff_g, ln_ff_b, xn);
    launch_gemm(1, xn, wt_w1, ffn_b1, hb, MROWS, FFN_DIM, DIM);
    launch_gemm(2, hb, wt_w2, ffn_b2, res, MROWS, DIM, FFN_DIM);
}